// round 17
// baseline (speedup 1.0000x reference)
#include <cuda_runtime.h>
#include <math.h>

#define B 8
#define M 12
#define NN 32
#define D 256
#define C 1024      // N*N
#define CH 512      // C/R
#define BM 96
#define GRID 296
#define NT 256

typedef unsigned long long ull;

// Scratch (allocation-free rule: device globals)
__device__ float g_S[BM * NN];     // row sums per bm
__device__ float g_U[NN * CH];     // [n][o] collapsed-GEMM1 weights
__device__ float g_cov[BM * C];    // centered cov (sign -> mask)
__device__ float g_att[BM * C];    // normalized attention
__device__ unsigned g_bcnt;        // barrier counter (returns to 0 each barrier)
__device__ int g_bgen;             // barrier generation (monotonic; replay-safe)

// ---- packed f32x2 helpers -------------------------------------------------
__device__ __forceinline__ ull ffma2(ull a, ull b, ull c) {
    ull d_;
    asm("fma.rn.f32x2 %0, %1, %2, %3;" : "=l"(d_) : "l"(a), "l"(b), "l"(c));
    return d_;
}
__device__ __forceinline__ ull pk2(float lo, float hi) {
    ull r;
    asm("mov.b64 %0, {%1, %2};" : "=l"(r) : "f"(lo), "f"(hi));
    return r;
}
__device__ __forceinline__ float unpk_add(ull v) {
    float lo, hi;
    asm("mov.b64 {%0, %1}, %2;" : "=f"(lo), "=f"(hi) : "l"(v));
    return lo + hi;
}
__device__ __forceinline__ void unpk2(ull v, float& lo, float& hi) {
    asm("mov.b64 {%0, %1}, %2;" : "=f"(lo), "=f"(hi) : "l"(v));
}

// smem swizzle: q in [0,128) float4 units within a 512-float row
#define SWZ(q) (((q) & 0x70) | (((q) ^ ((q) >> 4)) & 0x0F))
#define SWZ4(o) (SWZ((o) >> 2) * 4 + ((o) & 3))
#define XPAD 260   // floats per padded x row (= 65 float4)

// Grid-wide generation barrier. Safe: 296 blocks = 2/SM, ALL co-resident
// (enforced by __launch_bounds__(256,2) + 51KB smem). Monotonic generation
// flag -> any number of barriers per launch, graph-replay safe.
__device__ __forceinline__ void gbar() {
    __syncthreads();
    if (threadIdx.x == 0) {
        __threadfence();
        const int old = atomicAdd(&g_bgen, 0);   // read BEFORE arriving
        if (atomicAdd(&g_bcnt, 1) == GRID - 1) {
            g_bcnt = 0;
            __threadfence();
            atomicExch(&g_bgen, old + 1);
        } else {
            while (atomicAdd(&g_bgen, 0) == old) __nanosleep(32);
        }
        __threadfence();
    }
    __syncthreads();
}

// ---------------------------------------------------------------------------
__global__ void __launch_bounds__(NT, 2) kFused(const float* __restrict__ x,
                                                const float* __restrict__ W1,
                                                const float* __restrict__ W2,
                                                float* __restrict__ out) {
    extern __shared__ float sm[];
    const int bid = blockIdx.x;
    const int tid = threadIdx.x;
    const int w = tid >> 5, lane = tid & 31;

    // ======================= PHASE A =======================
    if (bid < 192) {
        // ---- cov half blocks: bm = bid>>1, rows [half*16, half*16+16) ----
        const int bm = bid >> 1;
        const int half = bid & 1;
        const int n0 = half * 16;
        float* xs  = sm;                 // padded natural [n*XPAD+d], 8320
        float* red = sm + 8320;          // 8 warps x 512 = 4096
        float* sp  = sm + 12416;         // 256
        float* S   = sm + 12672;         // 32

        const float4* xg4 = (const float4*)(x + (size_t)bm * (NN * D));
        float4* xs4 = (float4*)xs;
        #pragma unroll
        for (int t = 0; t < 8; t++) {
            const int i = tid + t * NT;
            const int n = i >> 6, q = i & 63;
            xs4[n * 65 + q] = xg4[i];    // conflict-free STS.128
        }
        __syncthreads();

        // xk = x[k=lane][w*32 .. w*32+31] via 8 LDS.128
        ull xk2[16];
        float spv = 0.f;
        const float4* xrow4 = (const float4*)(xs + lane * XPAD + w * 32);
        #pragma unroll
        for (int j = 0; j < 8; j++) {
            const float4 v = xrow4[j];
            xk2[2 * j]     = pk2(v.x, v.y);
            xk2[2 * j + 1] = pk2(v.z, v.w);
            spv += (v.x + v.y) + (v.z + v.w);
        }
        sp[w * 32 + lane] = spv;
        __syncthreads();
        if (tid < 32) {
            float s = 0.f;
            #pragma unroll
            for (int ww = 0; ww < 8; ww++) s += sp[ww * 32 + tid];
            S[tid] = s;
            if (half == 0) g_S[bm * NN + tid] = s;
        }
        __syncthreads();

        // cov partials for n in [n0, n0+16)
        ull acc2[16];
        #pragma unroll
        for (int nn = 0; nn < 16; nn++) acc2[nn] = 0ull;

        const ulonglong2* xs2 = (const ulonglong2*)xs;   // rows stride 65 f4
        #pragma unroll
        for (int nn = 0; nn < 16; nn++) {
            const ulonglong2* rowp = xs2 + (n0 + nn) * 65 + w * 8;
            #pragma unroll
            for (int jj = 0; jj < 8; jj++) {
                const ulonglong2 bv = rowp[jj];          // broadcast LDS.128
                acc2[nn] = ffma2(bv.x, xk2[2 * jj], acc2[nn]);
                acc2[nn] = ffma2(bv.y, xk2[2 * jj + 1], acc2[nn]);
            }
        }
        #pragma unroll
        for (int nn = 0; nn < 16; nn++)
            red[w * 512 + nn * 32 + lane] = unpk_add(acc2[nn]);
        __syncthreads();

        if (tid < 128) {   // combine 8 warp-partials, subtract S_n S_k / 256
            const float4* red4 = (const float4*)red;
            float4 cv = make_float4(0.f, 0.f, 0.f, 0.f);
            #pragma unroll
            for (int ww = 0; ww < 8; ww++) {
                const float4 t = red4[ww * 128 + tid];
                cv.x += t.x; cv.y += t.y; cv.z += t.z; cv.w += t.w;
            }
            const int n = n0 + (tid >> 3), k0 = (tid & 7) * 4;
            const float sn = S[n] * (1.f / 256.f);
            cv.x -= sn * S[k0 + 0]; cv.y -= sn * S[k0 + 1];
            cv.z -= sn * S[k0 + 2]; cv.w -= sn * S[k0 + 3];
            ((float4*)(g_cov + (size_t)bm * C + n0 * NN))[tid] = cv;
        }
    } else {
        // ---- U blocks (104): 5 o each ----
        const int ub = bid - 192;
        float* smT = sm + w * 1056;   // per-warp 33x32 transpose buf

        if (w < 5) {
            const int o = ub * 5 + w;
            if (o < CH) {
                const float* row = W1 + (size_t)o * C;
                float rr[32], cs = 0.f;
                #pragma unroll
                for (int j = 0; j < 32; j++) { rr[j] = row[j * 32 + lane]; cs += rr[j]; }
                #pragma unroll
                for (int j = 0; j < 32; j++) smT[j * 33 + lane] = rr[j];
                __syncwarp();
                float rs = 0.f;
                #pragma unroll
                for (int mm = 0; mm < 32; mm++) rs += smT[lane * 33 + mm];
                const float dg = smT[lane * 33 + lane];
                g_U[lane * CH + o] = rs + 2.f * cs - dg;   // lane = n
            }
        }
    }

    gbar();   // cov + S + U published

    // ============ PHASE B: e2 + softmax per att-row (blocks 0..255) ============
    if (bid < 256) {
        const int ctn = bid >> 3, b = bid & 7;   // att row n = ctn (0..31)
        float* hs     = sm;                      // 12 x 512 swizzled = 6144
        float* S12t   = sm + 6144;               // [n*12 + m], 384
        float* part   = sm + 6528;               // [kc][c*12+m], 8 x 387 = 3096
        float* att_sm = sm + 9624;               // [m*33 + cc], 396
        float* rinv   = sm + 10020;              // 12

        for (int i = tid; i < 384; i += NT) {
            const int m = i >> 5, n = i & 31;
            S12t[n * 12 + m] = g_S[(b * M + m) * NN + n];
        }
        __syncthreads();

        // h inline: thread owns o0 = tid, o1 = tid + 256
        {
            ull hacc[12];
            #pragma unroll
            for (int mm = 0; mm < 12; mm++) hacc[mm] = 0ull;
            #pragma unroll 4
            for (int n = 0; n < 32; n++) {
                const float u0 = g_U[n * CH + tid];
                const float u1 = g_U[n * CH + tid + 256];
                const ull u00 = pk2(u0, u0), u11 = pk2(u1, u1);
                #pragma unroll
                for (int mm = 0; mm < 6; mm++) {
                    const ull sv = *(const ull*)(S12t + n * 12 + 2 * mm);
                    hacc[mm]     = ffma2(sv, u00, hacc[mm]);
                    hacc[6 + mm] = ffma2(sv, u11, hacc[6 + mm]);
                }
            }
            const int so0 = SWZ4(tid), so1 = SWZ4(tid + 256);
            #pragma unroll
            for (int mm = 0; mm < 6; mm++) {
                float a, bb;
                unpk2(hacc[mm], a, bb);
                hs[(2 * mm) * 512 + so0]     = fmaxf(a  * (1.f / 512.f), 0.f);
                hs[(2 * mm + 1) * 512 + so0] = fmaxf(bb * (1.f / 512.f), 0.f);
                unpk2(hacc[6 + mm], a, bb);
                hs[(2 * mm) * 512 + so1]     = fmaxf(a  * (1.f / 512.f), 0.f);
                hs[(2 * mm + 1) * 512 + so1] = fmaxf(bb * (1.f / 512.f), 0.f);
            }
        }
        __syncthreads();

        // e2 GEMM: W2 row (ctn*32 + c) read straight to registers (MLP 16)
        const int c  = tid >> 3;          // 0..31 (= att element k)
        const int kc = tid & 7;           // k-chunk of 64 floats
        const int kc16 = kc * 16;
        const ulonglong2* w2r =
            (const ulonglong2*)(W2 + (size_t)(ctn * 32 + c) * CH);
        ulonglong2 wv[16];
        #pragma unroll
        for (int j = 0; j < 16; j++) wv[j] = w2r[kc16 + j];   // 16 indep LDG.128

        const ulonglong2* hu = (const ulonglong2*)hs;
        ull acc[12];
        #pragma unroll
        for (int m = 0; m < 12; m++) acc[m] = 0ull;

        #pragma unroll 4
        for (int j = 0; j < 16; j++) {
            const int qs = kc16 + ((j ^ kc) & 15);           // = SWZ(kc16+j)
            #pragma unroll
            for (int m = 0; m < 12; m++) {
                const ulonglong2 hv = hu[m * 128 + qs];      // multicast LDS
                acc[m] = ffma2(wv[j].x, hv.x, acc[m]);
                acc[m] = ffma2(wv[j].y, hv.y, acc[m]);
            }
        }
        __syncthreads();   // hs consumption done (part region is separate)

        #pragma unroll
        for (int m = 0; m < 12; m++)
            part[kc * 387 + c * 12 + m] = unpk_add(acc[m]);
        __syncthreads();

        // combine 384 outputs -> sigmoid -> mask -> exp
        #pragma unroll
        for (int t = 0; t < 2; t++) {
            const int i2 = tid + t * NT;        // = cc*12 + m, cc in 0..31
            if (i2 < 384) {
                const int cc = i2 / 12, m = i2 - 12 * cc;
                float e2v = 0.f;
                #pragma unroll
                for (int kk = 0; kk < 8; kk++) e2v += part[kk * 387 + i2];
                const float cvv = g_cov[(size_t)(b * M + m) * C + ctn * NN + cc];
                const float sg = 1.f / (1.f + __expf(-e2v));
                att_sm[m * 33 + cc] = (cvv > 0.f) ? __expf(sg) : 0.f;
            }
        }
        __syncthreads();

        // row sums (12 m rows), then normalized att out
        #pragma unroll
        for (int it = 0; it < 2; it++) {
            const int m = it * 8 + w;
            if (m < 12) {
                float v = att_sm[m * 33 + lane];
                #pragma unroll
                for (int off = 16; off; off >>= 1)
                    v += __shfl_xor_sync(0xffffffffu, v, off);
                if (lane == 0) rinv[m] = 1.f / v;
            }
        }
        __syncthreads();

        #pragma unroll
        for (int t = 0; t < 2; t++) {
            const int i2 = tid + t * NT;
            if (i2 < 384) {
                const int cc = i2 / 12, m = i2 - 12 * cc;
                g_att[(size_t)(b * M + m) * C + ctn * NN + cc] =
                    att_sm[m * 33 + cc] * rinv[m];
            }
        }
    }

    gbar();   // att published

    // ============ PHASE C: AV (blocks 0..191) ============
    if (bid < 192) {
        const int bm = bid >> 1;
        const int nh = bid & 1;          // n-half
        float* att = sm;                 // 16 x 32 = 512

        if (tid < 128)
            ((float4*)att)[tid] =
                ((const float4*)(g_att + (size_t)bm * C + nh * 512))[tid];

        // x column d=tid into regs (L2-warm)
        const float* xp = x + (size_t)bm * (NN * D) + tid;
        float xv[NN];
        #pragma unroll
        for (int k = 0; k < NN; k++) xv[k] = __ldg(xp + k * D);
        __syncthreads();

        ull xv2[16];
        #pragma unroll
        for (int kk = 0; kk < 16; kk++) xv2[kk] = pk2(xv[2 * kk], xv[2 * kk + 1]);

        float* ot = out + (size_t)bm * (NN * D) + nh * 16 * D;
        #pragma unroll 4
        for (int nn = 0; nn < 16; nn++) {
            const ulonglong2* ar = (const ulonglong2*)(att + nn * NN);
            ull a2 = 0ull;
            #pragma unroll
            for (int jj = 0; jj < 8; jj++) {
                const ulonglong2 bv = ar[jj];        // broadcast LDS.128
                a2 = ffma2(bv.x, xv2[2 * jj], a2);
                a2 = ffma2(bv.y, xv2[2 * jj + 1], a2);
            }
            ot[nn * D + tid] = unpk_add(a2);
        }
    }
}

// ---------------------------------------------------------------------------
extern "C" void kernel_launch(void* const* d_in, const int* in_sizes, int n_in,
                              void* d_out, int out_size) {
    const float* x  = (const float*)d_in[0];
    const float* W1 = (const float*)d_in[1];
    const float* W2 = (const float*)d_in[2];
    float* out = (float*)d_out;

    const int smem = 12704 * sizeof(float);   // 50,816 B -> 2 blocks/SM
    cudaFuncSetAttribute(kFused, cudaFuncAttributeMaxDynamicSharedMemorySize, smem);

    kFused<<<GRID, NT, smem>>>(x, W1, W2, out);
}